// round 3
// baseline (speedup 1.0000x reference)
#include <cuda_runtime.h>
#include <math.h>

// Problem constants
#define T_SEQ 4096
#define D_MODEL 2048
#define N_HEADS 16
#define N_KV 4
#define DH 128
#define HALF 64
#define KV_DIM 512   // N_KV * DH

// Scratch (device globals; no allocation allowed)
__device__ float g_q[T_SEQ * D_MODEL];
__device__ float g_k[T_SEQ * KV_DIM];
__device__ float g_v[T_SEQ * KV_DIM];
__device__ float g_y[T_SEQ * D_MODEL];

// ---------------------------------------------------------------------------
// SGEMM: C[M,N] = A[M,K] @ B[K,N], all row-major fp32.
// 128x128 tile, BK=16, 256 threads, 8x8 micro-tile per thread.
// ---------------------------------------------------------------------------
__global__ __launch_bounds__(256)
void sgemm128(const float* __restrict__ A, const float* __restrict__ B,
              float* __restrict__ C, int M, int N, int K) {
    __shared__ float As[16][132];   // [k][m], padded (2-way max on store)
    __shared__ float Bs[16][128];   // [k][n]

    const int tid = threadIdx.x;
    const int tx = tid & 15;        // n-group
    const int ty = tid >> 4;        // m-group
    const int m0 = blockIdx.y * 128;
    const int n0 = blockIdx.x * 128;

    float acc[8][8];
#pragma unroll
    for (int i = 0; i < 8; ++i)
#pragma unroll
        for (int j = 0; j < 8; ++j) acc[i][j] = 0.f;

    for (int k0 = 0; k0 < K; k0 += 16) {
        // Load A tile 128x16 (float4 along K, transposed store)
#pragma unroll
        for (int l = 0; l < 2; ++l) {
            int lin = tid + l * 256;        // float4 index, 512 total
            int r = lin >> 2;               // 0..127
            int kq = (lin & 3) << 2;        // 0,4,8,12
            float4 av = *(const float4*)(A + (size_t)(m0 + r) * K + k0 + kq);
            As[kq + 0][r] = av.x;
            As[kq + 1][r] = av.y;
            As[kq + 2][r] = av.z;
            As[kq + 3][r] = av.w;
        }
        // Load B tile 16x128 (float4 along N, direct)
#pragma unroll
        for (int l = 0; l < 2; ++l) {
            int lin = tid + l * 256;
            int r = lin >> 5;               // 0..15
            int c4 = (lin & 31) << 2;       // 0..124
            *(float4*)(&Bs[r][c4]) =
                *(const float4*)(B + (size_t)(k0 + r) * N + n0 + c4);
        }
        __syncthreads();

#pragma unroll
        for (int kk = 0; kk < 16; ++kk) {
            float4 a0 = *(float4*)(&As[kk][ty * 8]);
            float4 a1 = *(float4*)(&As[kk][ty * 8 + 4]);
            float4 b0 = *(float4*)(&Bs[kk][tx * 4]);
            float4 b1 = *(float4*)(&Bs[kk][64 + tx * 4]);
            float a[8] = {a0.x, a0.y, a0.z, a0.w, a1.x, a1.y, a1.z, a1.w};
            float b[8] = {b0.x, b0.y, b0.z, b0.w, b1.x, b1.y, b1.z, b1.w};
#pragma unroll
            for (int i = 0; i < 8; ++i)
#pragma unroll
                for (int j = 0; j < 8; ++j) acc[i][j] += a[i] * b[j];
        }
        __syncthreads();
    }

    // Write C: rows m0+ty*8+i, cols n0+tx*4+j (j<4) and n0+64+tx*4+(j-4)
#pragma unroll
    for (int i = 0; i < 8; ++i) {
        float* cp = C + (size_t)(m0 + ty * 8 + i) * N + n0;
        *(float4*)(cp + tx * 4)      = make_float4(acc[i][0], acc[i][1], acc[i][2], acc[i][3]);
        *(float4*)(cp + 64 + tx * 4) = make_float4(acc[i][4], acc[i][5], acc[i][6], acc[i][7]);
    }
}

// ---------------------------------------------------------------------------
// RoPE in-place on [T, nheads, 128] buffers (rowstride = nheads*128)
// ---------------------------------------------------------------------------
__global__ void rope_kernel(float* __restrict__ buf, int nheads, int rowstride) {
    int idx = blockIdx.x * blockDim.x + threadIdx.x;
    int total = T_SEQ * nheads * HALF;
    if (idx >= total) return;
    int i = idx & (HALF - 1);
    int h = (idx >> 6) % nheads;
    int t = idx / (HALF * nheads);

    float inv = powf(10000.f, -(float)i / (float)HALF);
    float ang = (float)t * inv;
    float s, c;
    sincosf(ang, &s, &c);

    float* base = buf + (size_t)t * rowstride + h * DH;
    float x1 = base[i];
    float x2 = base[i + HALF];
    base[i]        = x1 * c - x2 * s;
    base[i + HALF] = x1 * s + x2 * c;
}

// ---------------------------------------------------------------------------
// Flash attention (causal, GQA): per CTA one (query-block of 64, head).
// Qt/Kt stored d-major [128][64] with XOR swizzle for conflict-free LDS.128.
// Vs [64][128] natural, Pt [64][68] padded.
// 256 threads: tx=tid&15 (S cols / O cols), ty=tid>>4 (rows: ty*4..ty*4+3)
// ---------------------------------------------------------------------------
#define QT_OFF 0
#define KT_OFF 8192
#define VS_OFF 16384
#define PT_OFF 24576
#define SMEM_FLOATS (24576 + 64 * 68)
#define SMEM_BYTES (SMEM_FLOATS * 4)

__global__ __launch_bounds__(256)
void attn_kernel(const float* __restrict__ q, const float* __restrict__ k,
                 const float* __restrict__ v, float* __restrict__ y) {
    extern __shared__ float sm[];
    float* Qt = sm + QT_OFF;
    float* Kt = sm + KT_OFF;
    float* Vs = sm + VS_OFF;
    float* Pt = sm + PT_OFF;

    const int qb = blockIdx.x;          // query block (64 rows)
    const int hq = blockIdx.y;          // query head 0..15
    const int hkv = hq >> 2;            // kv head (GROUP = 4)
    const int tid = threadIdx.x;
    const int tx = tid & 15;
    const int ty = tid >> 4;
    const int q0 = qb * 64;

    // ---- Load Q tile transposed+swizzled: element (r,d) -> Qt[d][swz(r,d)]
#pragma unroll
    for (int l = 0; l < 8; ++l) {
        int lin = tid + l * 256;        // float4 index over 64x32
        int r = lin >> 5;               // query row in tile
        int d4 = lin & 31;
        int d = d4 << 2;
        float4 val = *(const float4*)(q + (size_t)(q0 + r) * D_MODEL + hq * DH + d);
        int g = r >> 2, ci = r & 3;
        int gs = (g ^ (d4 & 15)) << 2;
        Qt[(d + 0) * 64 + gs + ci] = val.x;
        Qt[(d + 1) * 64 + gs + ci] = val.y;
        Qt[(d + 2) * 64 + gs + ci] = val.z;
        Qt[(d + 3) * 64 + gs + ci] = val.w;
    }

    float m_i[4], l_i[4], acc[4][8];
#pragma unroll
    for (int i = 0; i < 4; ++i) {
        m_i[i] = -1e30f;
        l_i[i] = 0.f;
#pragma unroll
        for (int j = 0; j < 8; ++j) acc[i][j] = 0.f;
    }

    const float scale = 0.08838834764831845f;   // 1/sqrt(128)

    for (int jb = 0; jb <= qb; ++jb) {
        const int j0 = jb * 64;
        __syncthreads();   // protect Kt/Vs/Pt from previous iteration readers

        // Load K tile transposed+swizzled, V tile natural
#pragma unroll
        for (int l = 0; l < 8; ++l) {
            int lin = tid + l * 256;
            int r = lin >> 5;
            int d4 = lin & 31;
            int d = d4 << 2;
            float4 kv4 = *(const float4*)(k + (size_t)(j0 + r) * KV_DIM + hkv * DH + d);
            int g = r >> 2, ci = r & 3;
            int gs = (g ^ (d4 & 15)) << 2;
            Kt[(d + 0) * 64 + gs + ci] = kv4.x;
            Kt[(d + 1) * 64 + gs + ci] = kv4.y;
            Kt[(d + 2) * 64 + gs + ci] = kv4.z;
            Kt[(d + 3) * 64 + gs + ci] = kv4.w;
            float4 vv4 = *(const float4*)(v + (size_t)(j0 + r) * KV_DIM + hkv * DH + d);
            *(float4*)(Vs + r * 128 + d) = vv4;
        }
        __syncthreads();

        // ---- S = Q K^T fragment (4x4 per thread)
        float s[4][4];
#pragma unroll
        for (int i = 0; i < 4; ++i)
#pragma unroll
            for (int j = 0; j < 4; ++j) s[i][j] = 0.f;

#pragma unroll 4
        for (int d = 0; d < 128; ++d) {
            int d4 = d >> 2;
            float4 a = *(float4*)(Qt + d * 64 + ((ty ^ (d4 & 15)) << 2));
            float4 b = *(float4*)(Kt + d * 64 + ((tx ^ (d4 & 15)) << 2));
            float av[4] = {a.x, a.y, a.z, a.w};
            float bv[4] = {b.x, b.y, b.z, b.w};
#pragma unroll
            for (int i = 0; i < 4; ++i)
#pragma unroll
                for (int j = 0; j < 4; ++j) s[i][j] += av[i] * bv[j];
        }

        // scale + causal mask (diagonal block only)
        const bool diag = (jb == qb);
#pragma unroll
        for (int i = 0; i < 4; ++i) {
            int rl = ty * 4 + i;
#pragma unroll
            for (int j = 0; j < 4; ++j) {
                int cl = tx * 4 + j;
                float sv = s[i][j] * scale;
                if (diag && cl > rl) sv = -1e30f;
                s[i][j] = sv;
            }
        }

        // ---- online softmax per row (rows shared across the 16 tx lanes)
#pragma unroll
        for (int i = 0; i < 4; ++i) {
            float mx = fmaxf(fmaxf(s[i][0], s[i][1]), fmaxf(s[i][2], s[i][3]));
#pragma unroll
            for (int off = 1; off < 16; off <<= 1)
                mx = fmaxf(mx, __shfl_xor_sync(0xffffffffu, mx, off));
            float mnew = fmaxf(m_i[i], mx);
            float alpha = __expf(m_i[i] - mnew);
            float rs = 0.f;
#pragma unroll
            for (int j = 0; j < 4; ++j) {
                float p = __expf(s[i][j] - mnew);
                s[i][j] = p;
                rs += p;
            }
#pragma unroll
            for (int off = 1; off < 16; off <<= 1)
                rs += __shfl_xor_sync(0xffffffffu, rs, off);
            l_i[i] = l_i[i] * alpha + rs;
            m_i[i] = mnew;
#pragma unroll
            for (int j = 0; j < 8; ++j) acc[i][j] *= alpha;
        }

        // ---- write P transposed: Pt[c][r]
#pragma unroll
        for (int j = 0; j < 4; ++j) {
            *(float4*)(Pt + (tx * 4 + j) * 68 + ty * 4) =
                make_float4(s[0][j], s[1][j], s[2][j], s[3][j]);
        }
        __syncthreads();

        // ---- O += P V  (contraction over 64 keys)
#pragma unroll 4
        for (int c = 0; c < 64; ++c) {
            float4 a = *(float4*)(Pt + c * 68 + ty * 4);
            float4 b0 = *(float4*)(Vs + c * 128 + tx * 4);
            float4 b1 = *(float4*)(Vs + c * 128 + 64 + tx * 4);
            float av[4] = {a.x, a.y, a.z, a.w};
#pragma unroll
            for (int i = 0; i < 4; ++i) {
                acc[i][0] += av[i] * b0.x;
                acc[i][1] += av[i] * b0.y;
                acc[i][2] += av[i] * b0.z;
                acc[i][3] += av[i] * b0.w;
                acc[i][4] += av[i] * b1.x;
                acc[i][5] += av[i] * b1.y;
                acc[i][6] += av[i] * b1.z;
                acc[i][7] += av[i] * b1.w;
            }
        }
    }

    // ---- normalize & write y[t, hq*128 + dd]
#pragma unroll
    for (int i = 0; i < 4; ++i) {
        float inv = 1.f / l_i[i];
        int t = q0 + ty * 4 + i;
        float* yp = y + (size_t)t * D_MODEL + hq * DH;
        *(float4*)(yp + tx * 4) =
            make_float4(acc[i][0] * inv, acc[i][1] * inv, acc[i][2] * inv, acc[i][3] * inv);
        *(float4*)(yp + 64 + tx * 4) =
            make_float4(acc[i][4] * inv, acc[i][5] * inv, acc[i][6] * inv, acc[i][7] * inv);
    }
}

// ---------------------------------------------------------------------------
extern "C" void kernel_launch(void* const* d_in, const int* in_sizes, int n_in,
                              void* d_out, int out_size) {
    const float* x  = (const float*)d_in[0];
    const float* Wq = (const float*)d_in[1];
    const float* Wk = (const float*)d_in[2];
    const float* Wv = (const float*)d_in[3];
    const float* Wo = (const float*)d_in[4];
    float* out = (float*)d_out;

    void *pq, *pk, *pv, *py;
    cudaGetSymbolAddress(&pq, g_q);
    cudaGetSymbolAddress(&pk, g_k);
    cudaGetSymbolAddress(&pv, g_v);
    cudaGetSymbolAddress(&py, g_y);
    float* q = (float*)pq;
    float* kf = (float*)pk;
    float* vf = (float*)pv;
    float* y = (float*)py;

    // Projections
    sgemm128<<<dim3(D_MODEL / 128, T_SEQ / 128), 256>>>(x, Wq, q, T_SEQ, D_MODEL, D_MODEL);
    sgemm128<<<dim3(KV_DIM / 128, T_SEQ / 128), 256>>>(x, Wk, kf, T_SEQ, KV_DIM, D_MODEL);
    sgemm128<<<dim3(KV_DIM / 128, T_SEQ / 128), 256>>>(x, Wv, vf, T_SEQ, KV_DIM, D_MODEL);

    // RoPE
    {
        int nq = T_SEQ * N_HEADS * HALF;
        rope_kernel<<<(nq + 255) / 256, 256>>>(q, N_HEADS, D_MODEL);
        int nk = T_SEQ * N_KV * HALF;
        rope_kernel<<<(nk + 255) / 256, 256>>>(kf, N_KV, KV_DIM);
    }

    // Attention
    cudaFuncSetAttribute(attn_kernel, cudaFuncAttributeMaxDynamicSharedMemorySize, SMEM_BYTES);
    attn_kernel<<<dim3(T_SEQ / 64, N_HEADS), 256, SMEM_BYTES>>>(q, kf, vf, y);

    // Output projection
    sgemm128<<<dim3(D_MODEL / 128, T_SEQ / 128), 256>>>(y, Wo, out, T_SEQ, D_MODEL, D_MODEL);
}

// round 4
// speedup vs baseline: 1.0437x; 1.0437x over previous
#include <cuda_runtime.h>
#include <math.h>

// Problem constants
#define T_SEQ 4096
#define D_MODEL 2048
#define N_HEADS 16
#define N_KV 4
#define DH 128
#define HALF 64
#define KV_DIM 512   // N_KV * DH

typedef unsigned long long ull;

// Scratch (device globals; no allocation allowed)
__device__ float g_q[T_SEQ * D_MODEL];
__device__ float g_k[T_SEQ * KV_DIM];
__device__ float g_v[T_SEQ * KV_DIM];
__device__ float g_y[T_SEQ * D_MODEL];

// ---------------------------------------------------------------------------
// Packed f32x2 helpers (sm_100+): one issue slot = two fp32 FMAs.
// ---------------------------------------------------------------------------
__device__ __forceinline__ ull ffma2(ull a, ull b, ull c) {
    ull d;
    asm("fma.rn.f32x2 %0, %1, %2, %3;" : "=l"(d) : "l"(a), "l"(b), "l"(c));
    return d;
}
__device__ __forceinline__ ull mul2(ull a, ull b) {
    ull d;
    asm("mul.rn.f32x2 %0, %1, %2;" : "=l"(d) : "l"(a), "l"(b));
    return d;
}
__device__ __forceinline__ ull bcast2(float x) {
    ull d;
    asm("mov.b64 %0, {%1, %1};" : "=l"(d) : "f"(x));
    return d;
}
union F2U { ull u; float2 f; };

// ---------------------------------------------------------------------------
// SGEMM: C[M,N] = A[M,K] @ B[K,N], all row-major fp32.
// 128x128 tile, BK=16, 256 threads, 8x8 micro-tile per thread, f32x2 math.
// ---------------------------------------------------------------------------
__global__ __launch_bounds__(256)
void sgemm128(const float* __restrict__ A, const float* __restrict__ B,
              float* __restrict__ C, int M, int N, int K) {
    __shared__ float As[16][132];   // [k][m], padded
    __shared__ float Bs[16][128];   // [k][n]

    const int tid = threadIdx.x;
    const int tx = tid & 15;        // n-group
    const int ty = tid >> 4;        // m-group
    const int m0 = blockIdx.y * 128;
    const int n0 = blockIdx.x * 128;

    ull acc2[8][4];                 // 8 rows x 4 col-pairs
#pragma unroll
    for (int i = 0; i < 8; ++i)
#pragma unroll
        for (int j = 0; j < 4; ++j) acc2[i][j] = 0ull;

    for (int k0 = 0; k0 < K; k0 += 16) {
        // Load A tile 128x16 (float4 along K, transposed store)
#pragma unroll
        for (int l = 0; l < 2; ++l) {
            int lin = tid + l * 256;        // float4 index, 512 total
            int r = lin >> 2;               // 0..127
            int kq = (lin & 3) << 2;        // 0,4,8,12
            float4 av = *(const float4*)(A + (size_t)(m0 + r) * K + k0 + kq);
            As[kq + 0][r] = av.x;
            As[kq + 1][r] = av.y;
            As[kq + 2][r] = av.z;
            As[kq + 3][r] = av.w;
        }
        // Load B tile 16x128 (float4 along N, direct)
#pragma unroll
        for (int l = 0; l < 2; ++l) {
            int lin = tid + l * 256;
            int r = lin >> 5;               // 0..15
            int c4 = (lin & 31) << 2;       // 0..124
            *(float4*)(&Bs[r][c4]) =
                *(const float4*)(B + (size_t)(k0 + r) * N + n0 + c4);
        }
        __syncthreads();

#pragma unroll
        for (int kk = 0; kk < 16; ++kk) {
            float4 a0 = *(float4*)(&As[kk][ty * 8]);
            float4 a1 = *(float4*)(&As[kk][ty * 8 + 4]);
            ulonglong2 b0 = *(ulonglong2*)(&Bs[kk][tx * 4]);
            ulonglong2 b1 = *(ulonglong2*)(&Bs[kk][64 + tx * 4]);
            ull bb[4] = {b0.x, b0.y, b1.x, b1.y};
            float a[8] = {a0.x, a0.y, a0.z, a0.w, a1.x, a1.y, a1.z, a1.w};
#pragma unroll
            for (int i = 0; i < 8; ++i) {
                ull ai = bcast2(a[i]);
#pragma unroll
                for (int j = 0; j < 4; ++j)
                    acc2[i][j] = ffma2(ai, bb[j], acc2[i][j]);
            }
        }
        __syncthreads();
    }

    // Write C
#pragma unroll
    for (int i = 0; i < 8; ++i) {
        float* cp = C + (size_t)(m0 + ty * 8 + i) * N + n0;
        ulonglong2 o0, o1;
        o0.x = acc2[i][0]; o0.y = acc2[i][1];
        o1.x = acc2[i][2]; o1.y = acc2[i][3];
        *(ulonglong2*)(cp + tx * 4)      = o0;
        *(ulonglong2*)(cp + 64 + tx * 4) = o1;
    }
}

// ---------------------------------------------------------------------------
// RoPE in-place on [T, nheads, 128] buffers (rowstride = nheads*128)
// ---------------------------------------------------------------------------
__global__ void rope_kernel(float* __restrict__ buf, int nheads, int rowstride) {
    int idx = blockIdx.x * blockDim.x + threadIdx.x;
    int total = T_SEQ * nheads * HALF;
    if (idx >= total) return;
    int i = idx & (HALF - 1);
    int h = (idx >> 6) % nheads;
    int t = idx / (HALF * nheads);

    float inv = powf(10000.f, -(float)i / (float)HALF);
    float ang = (float)t * inv;
    float s, c;
    sincosf(ang, &s, &c);

    float* base = buf + (size_t)t * rowstride + h * DH;
    float x1 = base[i];
    float x2 = base[i + HALF];
    base[i]        = x1 * c - x2 * s;
    base[i + HALF] = x1 * s + x2 * c;
}

// ---------------------------------------------------------------------------
// Flash attention (causal, GQA): per CTA one (query-block of 64, head).
// Qt/Kt stored d-major [128][64] with XOR swizzle for conflict-free LDS.128.
// Vs [64][128] natural, Pt [64][68] padded. f32x2 packed math in both GEMMs.
// ---------------------------------------------------------------------------
#define QT_OFF 0
#define KT_OFF 8192
#define VS_OFF 16384
#define PT_OFF 24576
#define SMEM_FLOATS (24576 + 64 * 68)
#define SMEM_BYTES (SMEM_FLOATS * 4)

__global__ __launch_bounds__(256)
void attn_kernel(const float* __restrict__ q, const float* __restrict__ k,
                 const float* __restrict__ v, float* __restrict__ y) {
    extern __shared__ float sm[];
    float* Qt = sm + QT_OFF;
    float* Kt = sm + KT_OFF;
    float* Vs = sm + VS_OFF;
    float* Pt = sm + PT_OFF;

    const int qb = blockIdx.x;          // query block (64 rows)
    const int hq = blockIdx.y;          // query head 0..15
    const int hkv = hq >> 2;            // kv head (GROUP = 4)
    const int tid = threadIdx.x;
    const int tx = tid & 15;
    const int ty = tid >> 4;
    const int q0 = qb * 64;

    // ---- Load Q tile transposed+swizzled
#pragma unroll
    for (int l = 0; l < 8; ++l) {
        int lin = tid + l * 256;        // float4 index over 64x32
        int r = lin >> 5;
        int d4 = lin & 31;
        int d = d4 << 2;
        float4 val = *(const float4*)(q + (size_t)(q0 + r) * D_MODEL + hq * DH + d);
        int g = r >> 2, ci = r & 3;
        int gs = (g ^ (d4 & 15)) << 2;
        Qt[(d + 0) * 64 + gs + ci] = val.x;
        Qt[(d + 1) * 64 + gs + ci] = val.y;
        Qt[(d + 2) * 64 + gs + ci] = val.z;
        Qt[(d + 3) * 64 + gs + ci] = val.w;
    }

    float m_i[4], l_i[4];
    ull acc2[4][4];                     // 4 rows x 4 col-pairs (8 cols)
#pragma unroll
    for (int i = 0; i < 4; ++i) {
        m_i[i] = -1e30f;
        l_i[i] = 0.f;
#pragma unroll
        for (int j = 0; j < 4; ++j) acc2[i][j] = 0ull;
    }

    const float scale = 0.08838834764831845f;   // 1/sqrt(128)

    for (int jb = 0; jb <= qb; ++jb) {
        const int j0 = jb * 64;
        __syncthreads();   // protect Kt/Vs/Pt from previous iteration readers

        // Load K tile transposed+swizzled, V tile natural
#pragma unroll
        for (int l = 0; l < 8; ++l) {
            int lin = tid + l * 256;
            int r = lin >> 5;
            int d4 = lin & 31;
            int d = d4 << 2;
            float4 kv4 = *(const float4*)(k + (size_t)(j0 + r) * KV_DIM + hkv * DH + d);
            int g = r >> 2, ci = r & 3;
            int gs = (g ^ (d4 & 15)) << 2;
            Kt[(d + 0) * 64 + gs + ci] = kv4.x;
            Kt[(d + 1) * 64 + gs + ci] = kv4.y;
            Kt[(d + 2) * 64 + gs + ci] = kv4.z;
            Kt[(d + 3) * 64 + gs + ci] = kv4.w;
            float4 vv4 = *(const float4*)(v + (size_t)(j0 + r) * KV_DIM + hkv * DH + d);
            *(float4*)(Vs + r * 128 + d) = vv4;
        }
        __syncthreads();

        // ---- S = Q K^T fragment (4x4 per thread), packed along key cols
        ull s2[4][2];
#pragma unroll
        for (int i = 0; i < 4; ++i) { s2[i][0] = 0ull; s2[i][1] = 0ull; }

#pragma unroll 4
        for (int d = 0; d < 128; ++d) {
            int d4 = d >> 2;
            float4 a = *(float4*)(Qt + d * 64 + ((ty ^ (d4 & 15)) << 2));
            ulonglong2 b = *(ulonglong2*)(Kt + d * 64 + ((tx ^ (d4 & 15)) << 2));
            ull a0 = bcast2(a.x), a1 = bcast2(a.y), a2 = bcast2(a.z), a3 = bcast2(a.w);
            s2[0][0] = ffma2(a0, b.x, s2[0][0]); s2[0][1] = ffma2(a0, b.y, s2[0][1]);
            s2[1][0] = ffma2(a1, b.x, s2[1][0]); s2[1][1] = ffma2(a1, b.y, s2[1][1]);
            s2[2][0] = ffma2(a2, b.x, s2[2][0]); s2[2][1] = ffma2(a2, b.y, s2[2][1]);
            s2[3][0] = ffma2(a3, b.x, s2[3][0]); s2[3][1] = ffma2(a3, b.y, s2[3][1]);
        }

        // unpack, scale + causal mask (diagonal block only)
        float s[4][4];
        const bool diag = (jb == qb);
#pragma unroll
        for (int i = 0; i < 4; ++i) {
            F2U t0, t1;
            t0.u = s2[i][0]; t1.u = s2[i][1];
            s[i][0] = t0.f.x; s[i][1] = t0.f.y; s[i][2] = t1.f.x; s[i][3] = t1.f.y;
            int rl = ty * 4 + i;
#pragma unroll
            for (int j = 0; j < 4; ++j) {
                int cl = tx * 4 + j;
                float sv = s[i][j] * scale;
                if (diag && cl > rl) sv = -1e30f;
                s[i][j] = sv;
            }
        }

        // ---- online softmax per row (rows shared across the 16 tx lanes)
#pragma unroll
        for (int i = 0; i < 4; ++i) {
            float mx = fmaxf(fmaxf(s[i][0], s[i][1]), fmaxf(s[i][2], s[i][3]));
#pragma unroll
            for (int off = 1; off < 16; off <<= 1)
                mx = fmaxf(mx, __shfl_xor_sync(0xffffffffu, mx, off));
            float mnew = fmaxf(m_i[i], mx);
            float alpha = __expf(m_i[i] - mnew);
            float rs = 0.f;
#pragma unroll
            for (int j = 0; j < 4; ++j) {
                float p = __expf(s[i][j] - mnew);
                s[i][j] = p;
                rs += p;
            }
#pragma unroll
            for (int off = 1; off < 16; off <<= 1)
                rs += __shfl_xor_sync(0xffffffffu, rs, off);
            l_i[i] = l_i[i] * alpha + rs;
            m_i[i] = mnew;
            ull al2 = bcast2(alpha);
#pragma unroll
            for (int j = 0; j < 4; ++j) acc2[i][j] = mul2(acc2[i][j], al2);
        }

        // ---- write P transposed: Pt[c][r]
#pragma unroll
        for (int j = 0; j < 4; ++j) {
            *(float4*)(Pt + (tx * 4 + j) * 68 + ty * 4) =
                make_float4(s[0][j], s[1][j], s[2][j], s[3][j]);
        }
        __syncthreads();

        // ---- O += P V  (contraction over 64 keys), packed along head-dim cols
#pragma unroll 4
        for (int c = 0; c < 64; ++c) {
            float4 a = *(float4*)(Pt + c * 68 + ty * 4);
            ulonglong2 b0 = *(ulonglong2*)(Vs + c * 128 + tx * 4);
            ulonglong2 b1 = *(ulonglong2*)(Vs + c * 128 + 64 + tx * 4);
            ull av[4] = {bcast2(a.x), bcast2(a.y), bcast2(a.z), bcast2(a.w)};
#pragma unroll
            for (int i = 0; i < 4; ++i) {
                acc2[i][0] = ffma2(av[i], b0.x, acc2[i][0]);
                acc2[i][1] = ffma2(av[i], b0.y, acc2[i][1]);
                acc2[i][2] = ffma2(av[i], b1.x, acc2[i][2]);
                acc2[i][3] = ffma2(av[i], b1.y, acc2[i][3]);
            }
        }
    }

    // ---- normalize & write y[t, hq*128 + dd]
#pragma unroll
    for (int i = 0; i < 4; ++i) {
        ull inv2 = bcast2(1.f / l_i[i]);
        int t = q0 + ty * 4 + i;
        float* yp = y + (size_t)t * D_MODEL + hq * DH;
        ulonglong2 o0, o1;
        o0.x = mul2(acc2[i][0], inv2); o0.y = mul2(acc2[i][1], inv2);
        o1.x = mul2(acc2[i][2], inv2); o1.y = mul2(acc2[i][3], inv2);
        *(ulonglong2*)(yp + tx * 4)      = o0;
        *(ulonglong2*)(yp + 64 + tx * 4) = o1;
    }
}

// ---------------------------------------------------------------------------
extern "C" void kernel_launch(void* const* d_in, const int* in_sizes, int n_in,
                              void* d_out, int out_size) {
    const float* x  = (const float*)d_in[0];
    const float* Wq = (const float*)d_in[1];
    const float* Wk = (const float*)d_in[2];
    const float* Wv = (const float*)d_in[3];
    const float* Wo = (const float*)d_in[4];
    float* out = (float*)d_out;

    void *pq, *pk, *pv, *py;
    cudaGetSymbolAddress(&pq, g_q);
    cudaGetSymbolAddress(&pk, g_k);
    cudaGetSymbolAddress(&pv, g_v);
    cudaGetSymbolAddress(&py, g_y);
    float* q = (float*)pq;
    float* kf = (float*)pk;
    float* vf = (float*)pv;
    float* y = (float*)py;

    // Projections
    sgemm128<<<dim3(D_MODEL / 128, T_SEQ / 128), 256>>>(x, Wq, q, T_SEQ, D_MODEL, D_MODEL);
    sgemm128<<<dim3(KV_DIM / 128, T_SEQ / 128), 256>>>(x, Wk, kf, T_SEQ, KV_DIM, D_MODEL);
    sgemm128<<<dim3(KV_DIM / 128, T_SEQ / 128), 256>>>(x, Wv, vf, T_SEQ, KV_DIM, D_MODEL);

    // RoPE
    {
        int nq = T_SEQ * N_HEADS * HALF;
        rope_kernel<<<(nq + 255) / 256, 256>>>(q, N_HEADS, D_MODEL);
        int nk = T_SEQ * N_KV * HALF;
        rope_kernel<<<(nk + 255) / 256, 256>>>(kf, N_KV, KV_DIM);
    }

    // Attention
    cudaFuncSetAttribute(attn_kernel, cudaFuncAttributeMaxDynamicSharedMemorySize, SMEM_BYTES);
    attn_kernel<<<dim3(T_SEQ / 64, N_HEADS), 256, SMEM_BYTES>>>(q, kf, vf, y);

    // Output projection
    sgemm128<<<dim3(D_MODEL / 128, T_SEQ / 128), 256>>>(y, Wo, out, T_SEQ, D_MODEL, D_MODEL);
}

// round 6
// speedup vs baseline: 1.2494x; 1.1971x over previous
#include <cuda_runtime.h>
#include <math.h>
#include <cstdint>

// Problem constants
#define T_SEQ 4096
#define D_MODEL 2048
#define N_HEADS 16
#define N_KV 4
#define DH 128
#define HALF 64
#define KV_DIM 512   // N_KV * DH

typedef unsigned long long ull;

// Scratch (device globals; no allocation allowed)
__device__ float g_q[T_SEQ * D_MODEL];
__device__ float g_k[T_SEQ * KV_DIM];
__device__ float g_v[T_SEQ * KV_DIM];
__device__ float g_y[T_SEQ * D_MODEL];

// ---------------------------------------------------------------------------
// Packed f32x2 helpers (attention kernel)
// ---------------------------------------------------------------------------
__device__ __forceinline__ ull ffma2(ull a, ull b, ull c) {
    ull d;
    asm("fma.rn.f32x2 %0, %1, %2, %3;" : "=l"(d) : "l"(a), "l"(b), "l"(c));
    return d;
}
__device__ __forceinline__ ull mul2(ull a, ull b) {
    ull d;
    asm("mul.rn.f32x2 %0, %1, %2;" : "=l"(d) : "l"(a), "l"(b));
    return d;
}
__device__ __forceinline__ ull bcast2(float x) {
    ull d;
    asm("mov.b64 %0, {%1, %1};" : "=l"(d) : "f"(x));
    return d;
}
union F2U { ull u; float2 f; };

// ---------------------------------------------------------------------------
// tf32 helpers (mma.sync path — plain sm_80+ PTX, no arch-variant gating)
// ---------------------------------------------------------------------------
__device__ __forceinline__ uint32_t cvt_tf32(float f) {
    uint32_t u;
    asm("cvt.rna.tf32.f32 %0, %1;" : "=r"(u) : "f"(f));
    return u;
}

__device__ __forceinline__ void mma_tf32(float* d, const uint32_t* a,
                                         const uint32_t* b, const float* c) {
    asm volatile(
        "mma.sync.aligned.m16n8k8.row.col.f32.tf32.tf32.f32 "
        "{%0,%1,%2,%3}, {%4,%5,%6,%7}, {%8,%9}, {%10,%11,%12,%13};"
        : "=f"(d[0]), "=f"(d[1]), "=f"(d[2]), "=f"(d[3])
        : "r"(a[0]), "r"(a[1]), "r"(a[2]), "r"(a[3]),
          "r"(b[0]), "r"(b[1]),
          "f"(c[0]), "f"(c[1]), "f"(c[2]), "f"(c[3]));
}

// ---------------------------------------------------------------------------
// TF32 tensor-core GEMM: C[M,N] = A[M,K] @ B[K,N], fp32 in/out.
// CTA 128x128, BK=16, 256 threads = 8 warps (4m x 2n), warp tile 32x64.
// ---------------------------------------------------------------------------
__global__ __launch_bounds__(256)
void sgemm_tf32(const float* __restrict__ A, const float* __restrict__ B,
                float* __restrict__ C, int M, int N, int K) {
    __shared__ uint32_t As[128][20];    // [m][k], +4 pad
    __shared__ uint32_t Bs[16][132];    // [k][n], +4 pad

    const int tid = threadIdx.x;
    const int wid = tid >> 5;
    const int lane = tid & 31;
    const int g = lane >> 2;            // group 0..7
    const int t = lane & 3;             // thread-in-group 0..3
    const int m0 = blockIdx.y * 128;
    const int n0 = blockIdx.x * 128;
    const int wm = (wid & 3) * 32;      // warp m offset in tile
    const int wn = (wid >> 2) * 64;     // warp n offset in tile

    float acc[2][8][4];
#pragma unroll
    for (int mt = 0; mt < 2; ++mt)
#pragma unroll
        for (int nt = 0; nt < 8; ++nt)
#pragma unroll
            for (int r = 0; r < 4; ++r) acc[mt][nt][r] = 0.f;

    for (int k0 = 0; k0 < K; k0 += 16) {
        // ---- stage A: 128 rows x 16 k, cvt to tf32
#pragma unroll
        for (int l = 0; l < 2; ++l) {
            int idx = tid + l * 256;            // 512 float4
            int row = idx >> 2;
            int k4 = (idx & 3) << 2;
            float4 v = *(const float4*)(A + (size_t)(m0 + row) * K + k0 + k4);
            uint4 u;
            u.x = cvt_tf32(v.x); u.y = cvt_tf32(v.y);
            u.z = cvt_tf32(v.z); u.w = cvt_tf32(v.w);
            *(uint4*)(&As[row][k4]) = u;
        }
        // ---- stage B: 16 k x 128 n, cvt to tf32
#pragma unroll
        for (int l = 0; l < 2; ++l) {
            int idx = tid + l * 256;            // 512 float4
            int kk = idx >> 5;
            int n4 = (idx & 31) << 2;
            float4 v = *(const float4*)(B + (size_t)(k0 + kk) * N + n0 + n4);
            uint4 u;
            u.x = cvt_tf32(v.x); u.y = cvt_tf32(v.y);
            u.z = cvt_tf32(v.z); u.w = cvt_tf32(v.w);
            *(uint4*)(&Bs[kk][n4]) = u;
        }
        __syncthreads();

        // ---- two k8 steps
#pragma unroll
        for (int ks = 0; ks < 2; ++ks) {
            const int kk = ks * 8;
            uint32_t af[2][4];
#pragma unroll
            for (int mt = 0; mt < 2; ++mt) {
                const int r0 = wm + mt * 16;
                af[mt][0] = As[r0 + g][kk + t];
                af[mt][1] = As[r0 + g + 8][kk + t];
                af[mt][2] = As[r0 + g][kk + t + 4];
                af[mt][3] = As[r0 + g + 8][kk + t + 4];
            }
            uint32_t bf[8][2];
#pragma unroll
            for (int nt = 0; nt < 8; ++nt) {
                bf[nt][0] = Bs[kk + t][wn + nt * 8 + g];
                bf[nt][1] = Bs[kk + t + 4][wn + nt * 8 + g];
            }
#pragma unroll
            for (int mt = 0; mt < 2; ++mt)
#pragma unroll
                for (int nt = 0; nt < 8; ++nt)
                    mma_tf32(acc[mt][nt], af[mt], bf[nt], acc[mt][nt]);
        }
        __syncthreads();
    }

    // ---- epilogue: c0,c1 at (row g, col t*2), c2,c3 at (row g+8)
#pragma unroll
    for (int mt = 0; mt < 2; ++mt) {
        const int r0 = m0 + wm + mt * 16;
#pragma unroll
        for (int nt = 0; nt < 8; ++nt) {
            const int c0 = n0 + wn + nt * 8 + t * 2;
            *(float2*)(C + (size_t)(r0 + g) * N + c0) =
                make_float2(acc[mt][nt][0], acc[mt][nt][1]);
            *(float2*)(C + (size_t)(r0 + g + 8) * N + c0) =
                make_float2(acc[mt][nt][2], acc[mt][nt][3]);
        }
    }
}

// ---------------------------------------------------------------------------
// RoPE in-place on [T, nheads, 128] buffers (rowstride = nheads*128)
// ---------------------------------------------------------------------------
__global__ void rope_kernel(float* __restrict__ buf, int nheads, int rowstride) {
    int idx = blockIdx.x * blockDim.x + threadIdx.x;
    int total = T_SEQ * nheads * HALF;
    if (idx >= total) return;
    int i = idx & (HALF - 1);
    int h = (idx >> 6) % nheads;
    int t = idx / (HALF * nheads);

    float inv = powf(10000.f, -(float)i / (float)HALF);
    float ang = (float)t * inv;
    float s, c;
    sincosf(ang, &s, &c);

    float* base = buf + (size_t)t * rowstride + h * DH;
    float x1 = base[i];
    float x2 = base[i + HALF];
    base[i]        = x1 * c - x2 * s;
    base[i + HALF] = x1 * s + x2 * c;
}

// ---------------------------------------------------------------------------
// Flash attention (causal, GQA) — unchanged (passing, ~1.75ms)
// ---------------------------------------------------------------------------
#define QT_OFF 0
#define KT_OFF 8192
#define VS_OFF 16384
#define PT_OFF 24576
#define SMEM_FLOATS (24576 + 64 * 68)
#define SMEM_BYTES (SMEM_FLOATS * 4)

__global__ __launch_bounds__(256)
void attn_kernel(const float* __restrict__ q, const float* __restrict__ k,
                 const float* __restrict__ v, float* __restrict__ y) {
    extern __shared__ float sm[];
    float* Qt = sm + QT_OFF;
    float* Kt = sm + KT_OFF;
    float* Vs = sm + VS_OFF;
    float* Pt = sm + PT_OFF;

    const int qb = blockIdx.x;
    const int hq = blockIdx.y;
    const int hkv = hq >> 2;
    const int tid = threadIdx.x;
    const int tx = tid & 15;
    const int ty = tid >> 4;
    const int q0 = qb * 64;

#pragma unroll
    for (int l = 0; l < 8; ++l) {
        int lin = tid + l * 256;
        int r = lin >> 5;
        int d4 = lin & 31;
        int d = d4 << 2;
        float4 val = *(const float4*)(q + (size_t)(q0 + r) * D_MODEL + hq * DH + d);
        int g = r >> 2, ci = r & 3;
        int gs = (g ^ (d4 & 15)) << 2;
        Qt[(d + 0) * 64 + gs + ci] = val.x;
        Qt[(d + 1) * 64 + gs + ci] = val.y;
        Qt[(d + 2) * 64 + gs + ci] = val.z;
        Qt[(d + 3) * 64 + gs + ci] = val.w;
    }

    float m_i[4], l_i[4];
    ull acc2[4][4];
#pragma unroll
    for (int i = 0; i < 4; ++i) {
        m_i[i] = -1e30f;
        l_i[i] = 0.f;
#pragma unroll
        for (int j = 0; j < 4; ++j) acc2[i][j] = 0ull;
    }

    const float scale = 0.08838834764831845f;

    for (int jb = 0; jb <= qb; ++jb) {
        const int j0 = jb * 64;
        __syncthreads();

#pragma unroll
        for (int l = 0; l < 8; ++l) {
            int lin = tid + l * 256;
            int r = lin >> 5;
            int d4 = lin & 31;
            int d = d4 << 2;
            float4 kv4 = *(const float4*)(k + (size_t)(j0 + r) * KV_DIM + hkv * DH + d);
            int g = r >> 2, ci = r & 3;
            int gs = (g ^ (d4 & 15)) << 2;
            Kt[(d + 0) * 64 + gs + ci] = kv4.x;
            Kt[(d + 1) * 64 + gs + ci] = kv4.y;
            Kt[(d + 2) * 64 + gs + ci] = kv4.z;
            Kt[(d + 3) * 64 + gs + ci] = kv4.w;
            float4 vv4 = *(const float4*)(v + (size_t)(j0 + r) * KV_DIM + hkv * DH + d);
            *(float4*)(Vs + r * 128 + d) = vv4;
        }
        __syncthreads();

        ull s2[4][2];
#pragma unroll
        for (int i = 0; i < 4; ++i) { s2[i][0] = 0ull; s2[i][1] = 0ull; }

#pragma unroll 4
        for (int d = 0; d < 128; ++d) {
            int d4 = d >> 2;
            float4 a = *(float4*)(Qt + d * 64 + ((ty ^ (d4 & 15)) << 2));
            ulonglong2 b = *(ulonglong2*)(Kt + d * 64 + ((tx ^ (d4 & 15)) << 2));
            ull a0 = bcast2(a.x), a1 = bcast2(a.y), a2 = bcast2(a.z), a3 = bcast2(a.w);
            s2[0][0] = ffma2(a0, b.x, s2[0][0]); s2[0][1] = ffma2(a0, b.y, s2[0][1]);
            s2[1][0] = ffma2(a1, b.x, s2[1][0]); s2[1][1] = ffma2(a1, b.y, s2[1][1]);
            s2[2][0] = ffma2(a2, b.x, s2[2][0]); s2[2][1] = ffma2(a2, b.y, s2[2][1]);
            s2[3][0] = ffma2(a3, b.x, s2[3][0]); s2[3][1] = ffma2(a3, b.y, s2[3][1]);
        }

        float s[4][4];
        const bool diag = (jb == qb);
#pragma unroll
        for (int i = 0; i < 4; ++i) {
            F2U t0, t1;
            t0.u = s2[i][0]; t1.u = s2[i][1];
            s[i][0] = t0.f.x; s[i][1] = t0.f.y; s[i][2] = t1.f.x; s[i][3] = t1.f.y;
            int rl = ty * 4 + i;
#pragma unroll
            for (int j = 0; j < 4; ++j) {
                int cl = tx * 4 + j;
                float sv = s[i][j] * scale;
                if (diag && cl > rl) sv = -1e30f;
                s[i][j] = sv;
            }
        }

#pragma unroll
        for (int i = 0; i < 4; ++i) {
            float mx = fmaxf(fmaxf(s[i][0], s[i][1]), fmaxf(s[i][2], s[i][3]));
#pragma unroll
            for (int off = 1; off < 16; off <<= 1)
                mx = fmaxf(mx, __shfl_xor_sync(0xffffffffu, mx, off));
            float mnew = fmaxf(m_i[i], mx);
            float alpha = __expf(m_i[i] - mnew);
            float rs = 0.f;
#pragma unroll
            for (int j = 0; j < 4; ++j) {
                float p = __expf(s[i][j] - mnew);
                s[i][j] = p;
                rs += p;
            }
#pragma unroll
            for (int off = 1; off < 16; off <<= 1)
                rs += __shfl_xor_sync(0xffffffffu, rs, off);
            l_i[i] = l_i[i] * alpha + rs;
            m_i[i] = mnew;
            ull al2 = bcast2(alpha);
#pragma unroll
            for (int j = 0; j < 4; ++j) acc2[i][j] = mul2(acc2[i][j], al2);
        }

#pragma unroll
        for (int j = 0; j < 4; ++j) {
            *(float4*)(Pt + (tx * 4 + j) * 68 + ty * 4) =
                make_float4(s[0][j], s[1][j], s[2][j], s[3][j]);
        }
        __syncthreads();

#pragma unroll 4
        for (int c = 0; c < 64; ++c) {
            float4 a = *(float4*)(Pt + c * 68 + ty * 4);
            ulonglong2 b0 = *(ulonglong2*)(Vs + c * 128 + tx * 4);
            ulonglong2 b1 = *(ulonglong2*)(Vs + c * 128 + 64 + tx * 4);
            ull av[4] = {bcast2(a.x), bcast2(a.y), bcast2(a.z), bcast2(a.w)};
#pragma unroll
            for (int i = 0; i < 4; ++i) {
                acc2[i][0] = ffma2(av[i], b0.x, acc2[i][0]);
                acc2[i][1] = ffma2(av[i], b0.y, acc2[i][1]);
                acc2[i][2] = ffma2(av[i], b1.x, acc2[i][2]);
                acc2[i][3] = ffma2(av[i], b1.y, acc2[i][3]);
            }
        }
    }

#pragma unroll
    for (int i = 0; i < 4; ++i) {
        ull inv2 = bcast2(1.f / l_i[i]);
        int t = q0 + ty * 4 + i;
        float* yp = y + (size_t)t * D_MODEL + hq * DH;
        ulonglong2 o0, o1;
        o0.x = mul2(acc2[i][0], inv2); o0.y = mul2(acc2[i][1], inv2);
        o1.x = mul2(acc2[i][2], inv2); o1.y = mul2(acc2[i][3], inv2);
        *(ulonglong2*)(yp + tx * 4)      = o0;
        *(ulonglong2*)(yp + 64 + tx * 4) = o1;
    }
}

// ---------------------------------------------------------------------------
extern "C" void kernel_launch(void* const* d_in, const int* in_sizes, int n_in,
                              void* d_out, int out_size) {
    const float* x  = (const float*)d_in[0];
    const float* Wq = (const float*)d_in[1];
    const float* Wk = (const float*)d_in[2];
    const float* Wv = (const float*)d_in[3];
    const float* Wo = (const float*)d_in[4];
    float* out = (float*)d_out;

    void *pq, *pk, *pv, *py;
    cudaGetSymbolAddress(&pq, g_q);
    cudaGetSymbolAddress(&pk, g_k);
    cudaGetSymbolAddress(&pv, g_v);
    cudaGetSymbolAddress(&py, g_y);
    float* q = (float*)pq;
    float* kf = (float*)pk;
    float* vf = (float*)pv;
    float* y = (float*)py;

    // Projections (tf32 tensor cores via mma.sync)
    sgemm_tf32<<<dim3(D_MODEL / 128, T_SEQ / 128), 256>>>(x, Wq, q, T_SEQ, D_MODEL, D_MODEL);
    sgemm_tf32<<<dim3(KV_DIM / 128, T_SEQ / 128), 256>>>(x, Wk, kf, T_SEQ, KV_DIM, D_MODEL);
    sgemm_tf32<<<dim3(KV_DIM / 128, T_SEQ / 128), 256>>>(x, Wv, vf, T_SEQ, KV_DIM, D_MODEL);

    // RoPE
    {
        int nq = T_SEQ * N_HEADS * HALF;
        rope_kernel<<<(nq + 255) / 256, 256>>>(q, N_HEADS, D_MODEL);
        int nk = T_SEQ * N_KV * HALF;
        rope_kernel<<<(nk + 255) / 256, 256>>>(kf, N_KV, KV_DIM);
    }

    // Attention
    cudaFuncSetAttribute(attn_kernel, cudaFuncAttributeMaxDynamicSharedMemorySize, SMEM_BYTES);
    attn_kernel<<<dim3(T_SEQ / 64, N_HEADS), 256, SMEM_BYTES>>>(q, kf, vf, y);

    // Output projection
    sgemm_tf32<<<dim3(D_MODEL / 128, T_SEQ / 128), 256>>>(y, Wo, out, T_SEQ, D_MODEL, D_MODEL);
}